// round 11
// baseline (speedup 1.0000x reference)
#include <cuda_runtime.h>
#include <cstdint>

// MaxFeatBlockDescriptorLayer, fused single launch (R7 algorithm, half grid):
//   64 blocks x 512 threads; block (b,chunk) reduces 512 positions x 8
//   classes of prob in registers (thread = position, warp shuffle per class,
//   ballot for first-index ties), combines 16 warps via a 16x8 smem tile,
//   publishes ONE 16B slot per (b,class,chunk): {pack, sum, flag} with a
//   single st.global.cg.v4.
//   Blocks with chunk<8 also gather (class k = chunk): warp 0 polls its
//   class's 32 slots (1 per lane, nanosleep backoff, memory-clobbered .cg
//   ops), reduces, resets own slots (sole reader -> replay-safe), then 512
//   threads gather emb[b, argmax, :] * mask (1 float4 each).
//
// argmax tie-break = first index: ballot lowest lane in-warp; packed
// (bits(v)<<32)|(N_POS-1-idx) max across warps/chunks (prob >= 0 so float
// bits are order-monotonic).

#define N_POS    16384
#define N_CLS    8
#define C_DIM    2048
#define TAU      0.3f
#define CHUNKS   32
#define POS_PC   (N_POS / CHUNKS)        // 512
#define NTHREADS 512
#define NWARPS   (NTHREADS / 32)         // 16
#define MAX_B    8

// 16B slot: .x = pack lo, .y = pack hi, .z = sum bits, .w = flag
__device__ uint4 g_slot[MAX_B * N_CLS * CHUNKS];

__device__ __forceinline__ void slot_store(uint4* p, uint4 v) {
    asm volatile("st.global.cg.v4.u32 [%0], {%1,%2,%3,%4};"
                 :: "l"(p), "r"(v.x), "r"(v.y), "r"(v.z), "r"(v.w)
                 : "memory");
}
__device__ __forceinline__ uint4 slot_load(const uint4* p) {
    uint4 r;
    asm volatile("ld.global.cg.v4.u32 {%0,%1,%2,%3}, [%4];"
                 : "=r"(r.x), "=r"(r.y), "=r"(r.z), "=r"(r.w)
                 : "l"(p) : "memory");
    return r;
}

__global__ __launch_bounds__(NTHREADS)
void mfbd_fused(const float* __restrict__ emb,
                const float* __restrict__ prob,
                float* __restrict__ out)
{
    const int t    = threadIdx.x;
    const int w    = t >> 5;
    const int lane = t & 31;

    const int b     = blockIdx.x / CHUNKS;
    const int chunk = blockIdx.x % CHUNKS;

    __shared__ unsigned long long s_pk[NWARPS][N_CLS];   // [src warp][class]
    __shared__ float              s_sm[NWARPS][N_CLS];
    __shared__ int   s_arg;
    __shared__ float s_mask;

    // ---------------- Phase 1: thread = one position, regs only ----------------
    const float4* __restrict__ p4 =
        (const float4*)(prob + ((size_t)b * N_POS + (size_t)chunk * POS_PC) * N_CLS);
    const float4 a0 = __ldg(p4 + 2 * t);
    const float4 a1 = __ldg(p4 + 2 * t + 1);
    const float v[8] = { a0.x, a0.y, a0.z, a0.w, a1.x, a1.y, a1.z, a1.w };

    unsigned long long my_pk = 0ULL;
    float              my_sum = 0.0f;

    #pragma unroll
    for (int c = 0; c < N_CLS; ++c) {
        float m = v[c];
        float s = v[c];
        #pragma unroll
        for (int off = 16; off > 0; off >>= 1) {
            m = fmaxf(m, __shfl_xor_sync(0xffffffffu, m, off));
            s += __shfl_xor_sync(0xffffffffu, s, off);
        }
        const unsigned bal = __ballot_sync(0xffffffffu, v[c] == m);
        const int src  = __ffs(bal) - 1;                // lowest lane = first idx
        const int gidx = chunk * POS_PC + w * 32 + src;
        if (lane == c) {
            my_pk  = ((unsigned long long)__float_as_uint(m) << 32)
                   | (unsigned)(N_POS - 1 - gidx);
            my_sum = s;
        }
    }
    if (lane < N_CLS) {
        s_pk[w][lane] = my_pk;
        s_sm[w][lane] = my_sum;
    }
    __syncthreads();

    // ---- combine 16 warp-partials per class: warp w (<8) -> class w ----
    if (w < N_CLS && lane < NWARPS) {
        unsigned long long pk = s_pk[lane][w];
        float s = s_sm[lane][w];
        #pragma unroll
        for (int off = 8; off > 0; off >>= 1) {
            const unsigned long long o = __shfl_xor_sync(0xffffu, pk, off);
            pk = pk > o ? pk : o;
            s += __shfl_xor_sync(0xffffu, s, off);
        }
        if (lane == 0) {
            uint4 sl;
            sl.x = (unsigned)(pk & 0xffffffffu);
            sl.y = (unsigned)(pk >> 32);
            sl.z = __float_as_uint(s);
            sl.w = 1u;                                   // flag
            slot_store(&g_slot[(b * N_CLS + w) * CHUNKS + chunk], sl);
        }
    }

    // ---------------- Gather blocks: chunk < 8 -> class k = chunk ----------------
    if (chunk >= N_CLS) return;
    const int k = chunk;

    if (w == 0) {
        uint4* const base = &g_slot[(b * N_CLS + k) * CHUNKS];
        uint4 r0;
        for (;;) {
            r0 = slot_load(base + lane);                 // 32 slots, 1 per lane
            if (__all_sync(0xffffffffu, r0.w != 0u)) break;
            __nanosleep(64);
        }
        unsigned long long pk = ((unsigned long long)r0.y << 32) | r0.x;
        float s = __uint_as_float(r0.z);
        #pragma unroll
        for (int off = 16; off > 0; off >>= 1) {
            const unsigned long long o = __shfl_xor_sync(0xffffffffu, pk, off);
            pk = pk > o ? pk : o;
            s += __shfl_xor_sync(0xffffffffu, s, off);
        }
        if (lane == 0) {
            s_arg  = N_POS - 1 - (int)(unsigned)(pk & 0xffffffffu);
            s_mask = (s * (1.0f / N_POS) > TAU) ? 1.0f : 0.0f;
        }
        // replay-safe reset: this block is the sole reader of these slots
        // (ordered after the poll by the "memory" clobbers)
        slot_store(base + lane, make_uint4(0u, 0u, 0u, 0u));
    }
    __syncthreads();

    // ---------------- Gather emb[b, arg, :] * mask ----------------
    const float4* __restrict__ src =
        (const float4*)(emb + ((size_t)b * N_POS + (size_t)s_arg) * C_DIM);
    float4* __restrict__ dst =
        (float4*)(out + ((size_t)b * N_CLS + (size_t)k) * C_DIM);

    const float m = s_mask;
    float4 v0 = __ldg(src + t);                          // 512 float4, 1/thread
    v0.x *= m; v0.y *= m; v0.z *= m; v0.w *= m;
    dst[t] = v0;
}

extern "C" void kernel_launch(void* const* d_in, const int* in_sizes, int n_in,
                              void* d_out, int out_size)
{
    const float* emb  = (const float*)d_in[0];
    const float* prob = (const float*)d_in[1];
    float* out = (float*)d_out;

    const int B = in_sizes[0] / (N_POS * C_DIM);   // = 2

    mfbd_fused<<<B * CHUNKS, NTHREADS>>>(emb, prob, out);   // 64 blocks, 1 wave
}

// round 12
// speedup vs baseline: 1.0853x; 1.0853x over previous
#include <cuda_runtime.h>
#include <cstdint>

// MaxFeatBlockDescriptorLayer, fused single launch (R7 skeleton, leaner path):
//   64 blocks x 256 threads; block (b,chunk) reduces 512 positions x 8
//   classes of prob: 2 positions/thread local pre-reduce, warp shuffle per
//   class (ballot + idx shuffle for first-index ties), 8x8 smem combine,
//   publish ONE 16B slot per (b,class,chunk) via st.global.cg.v4.
//   Blocks with chunk<8 also gather (class k = chunk): ALL 8 warps poll the
//   32 slots redundantly (1 per lane, nanosleep backoff, memory-clobbered
//   .cg ops), butterfly-reduce so EVERY thread holds arg/mask in registers
//   -> emb loads issue immediately (no smem broadcast on the critical edge).
//   Slot reset happens after a syncthreads that is hidden under the emb
//   load latency (all warps passed the poll -> safe; sole-reader -> replay
//   safe).
//
// argmax tie-break = first index: local pair keeps earlier position on tie;
// ballot lowest lane in-warp; packed (bits(v)<<32)|(N_POS-1-idx) max across
// warps/chunks (prob >= 0 so float bits are order-monotonic).

#define N_POS    16384
#define N_CLS    8
#define C_DIM    2048
#define TAU      0.3f
#define CHUNKS   32
#define POS_PC   (N_POS / CHUNKS)        // 512
#define NTHREADS 256
#define MAX_B    8

// 16B slot: .x = pack lo, .y = pack hi, .z = sum bits, .w = flag
__device__ uint4 g_slot[MAX_B * N_CLS * CHUNKS];

__device__ __forceinline__ void slot_store(uint4* p, uint4 v) {
    asm volatile("st.global.cg.v4.u32 [%0], {%1,%2,%3,%4};"
                 :: "l"(p), "r"(v.x), "r"(v.y), "r"(v.z), "r"(v.w)
                 : "memory");
}
__device__ __forceinline__ uint4 slot_load(const uint4* p) {
    uint4 r;
    asm volatile("ld.global.cg.v4.u32 {%0,%1,%2,%3}, [%4];"
                 : "=r"(r.x), "=r"(r.y), "=r"(r.z), "=r"(r.w)
                 : "l"(p) : "memory");
    return r;
}

__global__ __launch_bounds__(NTHREADS)
void mfbd_fused(const float* __restrict__ emb,
                const float* __restrict__ prob,
                float* __restrict__ out)
{
    const int t    = threadIdx.x;
    const int w    = t >> 5;
    const int lane = t & 31;

    const int b     = blockIdx.x / CHUNKS;
    const int chunk = blockIdx.x % CHUNKS;

    __shared__ unsigned long long s_pk[N_CLS][N_CLS];   // [src warp][class]
    __shared__ float              s_sm[N_CLS][N_CLS];

    // ------------- Producer: 2 positions/thread, regs only -------------
    const float4* __restrict__ p4 =
        (const float4*)(prob + ((size_t)b * N_POS + (size_t)chunk * POS_PC) * N_CLS);
    const float4 a0 = __ldg(p4 + 4 * t);
    const float4 a1 = __ldg(p4 + 4 * t + 1);
    const float4 b0 = __ldg(p4 + 4 * t + 2);
    const float4 b1 = __ldg(p4 + 4 * t + 3);
    const float va[8] = { a0.x, a0.y, a0.z, a0.w, a1.x, a1.y, a1.z, a1.w };
    const float vb[8] = { b0.x, b0.y, b0.z, b0.w, b1.x, b1.y, b1.z, b1.w };

    unsigned long long my_pk = 0ULL;
    float              my_sum = 0.0f;

    #pragma unroll
    for (int c = 0; c < N_CLS; ++c) {
        // local pair reduce (strict > keeps the earlier position on ties)
        const float    vm  = fmaxf(va[c], vb[c]);
        const unsigned off = (vb[c] > va[c]) ? 1u : 0u;
        float s = va[c] + vb[c];

        float m = vm;
        #pragma unroll
        for (int o = 16; o > 0; o >>= 1) {
            m = fmaxf(m, __shfl_xor_sync(0xffffffffu, m, o));
            s += __shfl_xor_sync(0xffffffffu, s, o);
        }
        const unsigned bal = __ballot_sync(0xffffffffu, vm == m);
        const int src = __ffs(bal) - 1;                     // lowest lane
        const unsigned soff = __shfl_sync(0xffffffffu, off, src);
        const int gidx = chunk * POS_PC + (w * 32 + src) * 2 + (int)soff;
        if (lane == c) {
            my_pk  = ((unsigned long long)__float_as_uint(m) << 32)
                   | (unsigned)(N_POS - 1 - gidx);
            my_sum = s;
        }
    }
    if (lane < N_CLS) {
        s_pk[w][lane] = my_pk;
        s_sm[w][lane] = my_sum;
    }
    __syncthreads();

    // ---- combine 8 warp-partials per class: warp w -> class w, lanes 0..7 ----
    if (lane < N_CLS) {
        unsigned long long pk = s_pk[lane][w];
        float s = s_sm[lane][w];
        #pragma unroll
        for (int o = 4; o > 0; o >>= 1) {
            const unsigned long long x = __shfl_xor_sync(0xffu, pk, o);
            pk = pk > x ? pk : x;
            s += __shfl_xor_sync(0xffu, s, o);
        }
        if (lane == 0) {
            uint4 sl;
            sl.x = (unsigned)(pk & 0xffffffffu);
            sl.y = (unsigned)(pk >> 32);
            sl.z = __float_as_uint(s);
            sl.w = 1u;                                       // flag
            slot_store(&g_slot[(b * N_CLS + w) * CHUNKS + chunk], sl);
        }
    }

    // ------------- Gather blocks: chunk < 8 -> class k = chunk -------------
    if (chunk >= N_CLS) return;
    const int k = chunk;

    uint4* const base = &g_slot[(b * N_CLS + k) * CHUNKS];

    // ALL warps poll redundantly: 32 slots, 1 per lane.
    uint4 r0;
    for (;;) {
        r0 = slot_load(base + lane);
        if (__all_sync(0xffffffffu, r0.w != 0u)) break;
        __nanosleep(32);
    }
    // Butterfly reduce -> every lane ends with the final pk/s.
    unsigned long long pk = ((unsigned long long)r0.y << 32) | r0.x;
    float s = __uint_as_float(r0.z);
    #pragma unroll
    for (int o = 16; o > 0; o >>= 1) {
        const unsigned long long x = __shfl_xor_sync(0xffffffffu, pk, o);
        pk = pk > x ? pk : x;
        s += __shfl_xor_sync(0xffffffffu, s, o);
    }
    const int   arg  = N_POS - 1 - (int)(unsigned)(pk & 0xffffffffu);
    const float mask = (s * (1.0f / N_POS) > TAU) ? 1.0f : 0.0f;

    // Issue emb loads immediately (critical path).
    const float4* __restrict__ src =
        (const float4*)(emb + ((size_t)b * N_POS + (size_t)arg) * C_DIM);
    float4* __restrict__ dst =
        (float4*)(out + ((size_t)b * N_CLS + (size_t)k) * C_DIM);

    float4 v0 = __ldg(src + t);
    float4 v1 = __ldg(src + t + NTHREADS);

    // Reset own slots off the critical path (hidden under emb load latency).
    // syncthreads: all warps have passed the poll before any reset.
    __syncthreads();
    if (w == 0) slot_store(base + lane, make_uint4(0u, 0u, 0u, 0u));

    v0.x *= mask; v0.y *= mask; v0.z *= mask; v0.w *= mask;
    v1.x *= mask; v1.y *= mask; v1.z *= mask; v1.w *= mask;
    dst[t]            = v0;
    dst[t + NTHREADS] = v1;
}

extern "C" void kernel_launch(void* const* d_in, const int* in_sizes, int n_in,
                              void* d_out, int out_size)
{
    const float* emb  = (const float*)d_in[0];
    const float* prob = (const float*)d_in[1];
    float* out = (float*)d_out;

    const int B = in_sizes[0] / (N_POS * C_DIM);   // = 2

    mfbd_fused<<<B * CHUNKS, NTHREADS>>>(emb, prob, out);   // 64 blocks, 1 wave
}

// round 13
// speedup vs baseline: 1.1111x; 1.0238x over previous
#include <cuda_runtime.h>
#include <cstdint>

// MaxFeatBlockDescriptorLayer, fused single launch (R11 skeleton, split-reduce):
//   64 blocks x 256 threads; block (b,chunk) reduces 512 positions x 8
//   classes of prob. Per thread: 2 positions -> local pair reduce -> pack
//   (bits(v)<<32 | N_POS-1-idx) per class. Warp reduction via VALUE-SPLITTING
//   butterfly (xor16/8/4 halve classes per lane, xor2/1 finish): 27 shuffles,
//   no ballots. 8x8 smem combine, publish ONE 16B slot per (b,class,chunk)
//   via st.global.cg.v4.
//   Blocks with chunk<8 also gather (class k = chunk): ALL 8 warps poll the
//   32 slots redundantly (1/lane, nanosleep, memory-clobbered .cg ops),
//   butterfly-reduce so every thread holds arg/mask in registers -> emb
//   loads issue immediately; slot reset deferred under emb load latency.
//
// argmax tie-break = first index: local pair keeps earlier position on tie;
// packed max (comp index decreasing in n) handles lanes/warps/chunks
// (prob >= 0 so float bits are order-monotonic).

#define N_POS    16384
#define N_CLS    8
#define C_DIM    2048
#define TAU      0.3f
#define CHUNKS   32
#define POS_PC   (N_POS / CHUNKS)        // 512
#define NTHREADS 256
#define MAX_B    8

// 16B slot: .x = pack lo, .y = pack hi, .z = sum bits, .w = flag
__device__ uint4 g_slot[MAX_B * N_CLS * CHUNKS];

__device__ __forceinline__ void slot_store(uint4* p, uint4 v) {
    asm volatile("st.global.cg.v4.u32 [%0], {%1,%2,%3,%4};"
                 :: "l"(p), "r"(v.x), "r"(v.y), "r"(v.z), "r"(v.w)
                 : "memory");
}
__device__ __forceinline__ uint4 slot_load(const uint4* p) {
    uint4 r;
    asm volatile("ld.global.cg.v4.u32 {%0,%1,%2,%3}, [%4];"
                 : "=r"(r.x), "=r"(r.y), "=r"(r.z), "=r"(r.w)
                 : "l"(p) : "memory");
    return r;
}
__device__ __forceinline__ unsigned long long umax64(unsigned long long a,
                                                     unsigned long long b) {
    return a > b ? a : b;
}

__global__ __launch_bounds__(NTHREADS)
void mfbd_fused(const float* __restrict__ emb,
                const float* __restrict__ prob,
                float* __restrict__ out)
{
    const int t    = threadIdx.x;
    const int w    = t >> 5;
    const int lane = t & 31;

    const int b     = blockIdx.x / CHUNKS;
    const int chunk = blockIdx.x % CHUNKS;

    __shared__ unsigned long long s_pk[N_CLS][N_CLS];   // [src warp][class]
    __shared__ float              s_sm[N_CLS][N_CLS];

    // ------------- Producer: 2 positions/thread, pack locally -------------
    const float4* __restrict__ p4 =
        (const float4*)(prob + ((size_t)b * N_POS + (size_t)chunk * POS_PC) * N_CLS);
    const float4 a0 = __ldg(p4 + 4 * t);
    const float4 a1 = __ldg(p4 + 4 * t + 1);
    const float4 b0 = __ldg(p4 + 4 * t + 2);
    const float4 b1 = __ldg(p4 + 4 * t + 3);
    const float va[8] = { a0.x, a0.y, a0.z, a0.w, a1.x, a1.y, a1.z, a1.w };
    const float vb[8] = { b0.x, b0.y, b0.z, b0.w, b1.x, b1.y, b1.z, b1.w };

    const int pos0 = chunk * POS_PC + 2 * t;

    unsigned long long pk8[8];
    float              sm8[8];
    #pragma unroll
    for (int c = 0; c < N_CLS; ++c) {
        const float    vm  = fmaxf(va[c], vb[c]);
        const unsigned off = (vb[c] > va[c]) ? 1u : 0u;   // tie -> earlier pos
        pk8[c] = ((unsigned long long)__float_as_uint(vm) << 32)
               | (unsigned)(N_POS - 1 - (pos0 + (int)off));
        sm8[c] = va[c] + vb[c];
    }

    // ---- value-splitting butterfly: xor16 (8->4), xor8 (4->2), xor4 (2->1) ----
    unsigned long long pk4[4]; float sm4[4];
    {
        const bool hi = (lane & 16) != 0;
        #pragma unroll
        for (int i = 0; i < 4; ++i) {
            const unsigned long long sendp = hi ? pk8[i] : pk8[i + 4];
            const unsigned long long keepp = hi ? pk8[i + 4] : pk8[i];
            const float sends = hi ? sm8[i] : sm8[i + 4];
            const float keeps = hi ? sm8[i + 4] : sm8[i];
            pk4[i] = umax64(keepp, __shfl_xor_sync(0xffffffffu, sendp, 16));
            sm4[i] = keeps + __shfl_xor_sync(0xffffffffu, sends, 16);
        }
    }
    unsigned long long pk2[2]; float sm2[2];
    {
        const bool hi = (lane & 8) != 0;
        #pragma unroll
        for (int i = 0; i < 2; ++i) {
            const unsigned long long sendp = hi ? pk4[i] : pk4[i + 2];
            const unsigned long long keepp = hi ? pk4[i + 2] : pk4[i];
            const float sends = hi ? sm4[i] : sm4[i + 2];
            const float keeps = hi ? sm4[i + 2] : sm4[i];
            pk2[i] = umax64(keepp, __shfl_xor_sync(0xffffffffu, sendp, 8));
            sm2[i] = keeps + __shfl_xor_sync(0xffffffffu, sends, 8);
        }
    }
    unsigned long long pk1; float sm1;
    {
        const bool hi = (lane & 4) != 0;
        const unsigned long long sendp = hi ? pk2[0] : pk2[1];
        const unsigned long long keepp = hi ? pk2[1] : pk2[0];
        const float sends = hi ? sm2[0] : sm2[1];
        const float keeps = hi ? sm2[1] : sm2[0];
        pk1 = umax64(keepp, __shfl_xor_sync(0xffffffffu, sendp, 4));
        sm1 = keeps + __shfl_xor_sync(0xffffffffu, sends, 4);
    }
    // finish over lane bits 1,0 (lanes 4c..4c+3 share class c = (lane>>2)&7)
    #pragma unroll
    for (int o = 2; o > 0; o >>= 1) {
        pk1 = umax64(pk1, __shfl_xor_sync(0xffffffffu, pk1, o));
        sm1 += __shfl_xor_sync(0xffffffffu, sm1, o);
    }

    if ((lane & 3) == 0) {
        const int c = (lane >> 2) & 7;
        s_pk[w][c] = pk1;
        s_sm[w][c] = sm1;
    }
    __syncthreads();

    // ---- combine 8 warp-partials per class: warp w -> class w, lanes 0..7 ----
    if (lane < N_CLS) {
        unsigned long long pk = s_pk[lane][w];
        float s = s_sm[lane][w];
        #pragma unroll
        for (int o = 4; o > 0; o >>= 1) {
            pk = umax64(pk, __shfl_xor_sync(0xffu, pk, o));
            s += __shfl_xor_sync(0xffu, s, o);
        }
        if (lane == 0) {
            uint4 sl;
            sl.x = (unsigned)(pk & 0xffffffffu);
            sl.y = (unsigned)(pk >> 32);
            sl.z = __float_as_uint(s);
            sl.w = 1u;                                   // flag
            slot_store(&g_slot[(b * N_CLS + w) * CHUNKS + chunk], sl);
        }
    }

    // ------------- Gather blocks: chunk < 8 -> class k = chunk -------------
    if (chunk >= N_CLS) return;
    const int k = chunk;

    uint4* const base = &g_slot[(b * N_CLS + k) * CHUNKS];

    // ALL warps poll redundantly: 32 slots, 1 per lane.
    uint4 r0;
    for (;;) {
        r0 = slot_load(base + lane);
        if (__all_sync(0xffffffffu, r0.w != 0u)) break;
        __nanosleep(32);
    }
    // Butterfly reduce -> every lane ends with the final pk/s.
    unsigned long long pk = ((unsigned long long)r0.y << 32) | r0.x;
    float s = __uint_as_float(r0.z);
    #pragma unroll
    for (int o = 16; o > 0; o >>= 1) {
        pk = umax64(pk, __shfl_xor_sync(0xffffffffu, pk, o));
        s += __shfl_xor_sync(0xffffffffu, s, o);
    }
    const int   arg  = N_POS - 1 - (int)(unsigned)(pk & 0xffffffffu);
    const float mask = (s * (1.0f / N_POS) > TAU) ? 1.0f : 0.0f;

    // Issue emb loads immediately (critical path).
    const float4* __restrict__ src =
        (const float4*)(emb + ((size_t)b * N_POS + (size_t)arg) * C_DIM);
    float4* __restrict__ dst =
        (float4*)(out + ((size_t)b * N_CLS + (size_t)k) * C_DIM);

    float4 v0 = __ldg(src + t);
    float4 v1 = __ldg(src + t + NTHREADS);

    // Reset own slots off the critical path (hidden under emb load latency).
    __syncthreads();
    if (w == 0) slot_store(base + lane, make_uint4(0u, 0u, 0u, 0u));

    v0.x *= mask; v0.y *= mask; v0.z *= mask; v0.w *= mask;
    v1.x *= mask; v1.y *= mask; v1.z *= mask; v1.w *= mask;
    dst[t]            = v0;
    dst[t + NTHREADS] = v1;
}

extern "C" void kernel_launch(void* const* d_in, const int* in_sizes, int n_in,
                              void* d_out, int out_size)
{
    const float* emb  = (const float*)d_in[0];
    const float* prob = (const float*)d_in[1];
    float* out = (float*)d_out;

    const int B = in_sizes[0] / (N_POS * C_DIM);   // = 2

    mfbd_fused<<<B * CHUNKS, NTHREADS>>>(emb, prob, out);   // 64 blocks, 1 wave
}

// round 14
// speedup vs baseline: 1.3527x; 1.2174x over previous
#include <cuda_runtime.h>
#include <cstdint>

// MaxFeatBlockDescriptorLayer, fused single launch (R12 skeleton, redux.sync):
//   64 blocks x 256 threads; block (b,chunk) reduces 512 positions x 8
//   classes of prob. Per thread: 2 positions -> local pair reduce. Per class:
//   redux.max.u32 on float bits + ballot + redux.max.u32 on complemented
//   index among candidates (exact first-index), fixed-point redux.add.u32
//   for the sum (scale 2^16). 8x8 smem combine also redux-based (mask 0xff).
//   Publish ONE 16B slot per (b,class,chunk) via st.global.cg.v4.
//   Blocks with chunk<8 also gather (class k = chunk): ALL 8 warps poll the
//   32 slots redundantly (1/lane, nanosleep, memory-clobbered .cg ops),
//   redux-reduce so every thread holds arg/mask in registers -> emb loads
//   issue immediately; slot reset deferred under emb load latency.
//
// Exactness: argmax identical to jnp.argmax (first index). Mask uses a
// fixed-point sum: per-element rounding <= 0.5/65536, total error ~1e-5
// relative -- cannot flip (mean~0.5 vs tau=0.3). Masked emb rows exact.

#define N_POS    16384
#define N_CLS    8
#define C_DIM    2048
#define CHUNKS   32
#define POS_PC   (N_POS / CHUNKS)        // 512
#define NTHREADS 256
#define MAX_B    8
// mask threshold: sum_fixed > TAU * N_POS * 2^16 = 0.3 * 16384 * 65536
#define TAU_FIXED 322122547u

// 16B slot: .x = pack lo (comp idx), .y = pack hi (val bits), .z = fixed sum, .w = flag
__device__ uint4 g_slot[MAX_B * N_CLS * CHUNKS];

__device__ __forceinline__ void slot_store(uint4* p, uint4 v) {
    asm volatile("st.global.cg.v4.u32 [%0], {%1,%2,%3,%4};"
                 :: "l"(p), "r"(v.x), "r"(v.y), "r"(v.z), "r"(v.w)
                 : "memory");
}
__device__ __forceinline__ uint4 slot_load(const uint4* p) {
    uint4 r;
    asm volatile("ld.global.cg.v4.u32 {%0,%1,%2,%3}, [%4];"
                 : "=r"(r.x), "=r"(r.y), "=r"(r.z), "=r"(r.w)
                 : "l"(p) : "memory");
    return r;
}
__device__ __forceinline__ unsigned redux_max(unsigned v, unsigned mask) {
    unsigned d;
    asm volatile("redux.sync.max.u32 %0, %1, %2;" : "=r"(d) : "r"(v), "r"(mask));
    return d;
}
__device__ __forceinline__ unsigned redux_add(unsigned v, unsigned mask) {
    unsigned d;
    asm volatile("redux.sync.add.u32 %0, %1, %2;" : "=r"(d) : "r"(v), "r"(mask));
    return d;
}

__global__ __launch_bounds__(NTHREADS)
void mfbd_fused(const float* __restrict__ emb,
                const float* __restrict__ prob,
                float* __restrict__ out)
{
    const int t    = threadIdx.x;
    const int w    = t >> 5;
    const int lane = t & 31;

    const int b     = blockIdx.x / CHUNKS;
    const int chunk = blockIdx.x % CHUNKS;

    __shared__ unsigned s_hi[N_CLS][N_CLS];   // [src warp][class] value bits
    __shared__ unsigned s_lo[N_CLS][N_CLS];   // [src warp][class] comp idx
    __shared__ unsigned s_fx[N_CLS][N_CLS];   // [src warp][class] fixed sum

    // ------------- Producer: 2 positions/thread, regs only -------------
    const float4* __restrict__ p4 =
        (const float4*)(prob + ((size_t)b * N_POS + (size_t)chunk * POS_PC) * N_CLS);
    const float4 a0 = __ldg(p4 + 4 * t);
    const float4 a1 = __ldg(p4 + 4 * t + 1);
    const float4 b0 = __ldg(p4 + 4 * t + 2);
    const float4 b1 = __ldg(p4 + 4 * t + 3);
    const float va[8] = { a0.x, a0.y, a0.z, a0.w, a1.x, a1.y, a1.z, a1.w };
    const float vb[8] = { b0.x, b0.y, b0.z, b0.w, b1.x, b1.y, b1.z, b1.w };

    const int pos0 = chunk * POS_PC + 2 * t;

    unsigned hi8[8], lo8[8], fx8[8];
    #pragma unroll
    for (int c = 0; c < N_CLS; ++c) {
        // local pair reduce (strict > keeps earlier position on ties)
        const float    vm   = fmaxf(va[c], vb[c]);
        const unsigned off  = (vb[c] > va[c]) ? 1u : 0u;
        const unsigned bits = __float_as_uint(vm);
        const unsigned comp = (unsigned)(N_POS - 1 - (pos0 + (int)off));
        const unsigned sfx  = (unsigned)__float2uint_rn((va[c] + vb[c]) * 65536.0f);

        // warp reduce via redux: depth 3 collectives, no shuffles
        const unsigned mx   = redux_max(bits, 0xffffffffu);
        const unsigned cand = (bits == mx) ? comp : 0u;
        hi8[c] = mx;
        lo8[c] = redux_max(cand, 0xffffffffu);    // largest comp = first index
        fx8[c] = redux_add(sfx, 0xffffffffu);
    }
    if (lane < N_CLS) {                            // lane c holds class c copy
        s_hi[w][lane] = hi8[lane];
        s_lo[w][lane] = lo8[lane];
        s_fx[w][lane] = fx8[lane];
    }
    __syncthreads();

    // ---- combine 8 warp-partials per class: warp w -> class w, lanes 0..7 ----
    if (lane < N_CLS) {
        const unsigned hi = s_hi[lane][w];
        const unsigned lo = s_lo[lane][w];
        const unsigned fx = s_fx[lane][w];
        const unsigned mx   = redux_max(hi, 0xffu);
        const unsigned cand = (hi == mx) ? lo : 0u;
        const unsigned mlo  = redux_max(cand, 0xffu);
        const unsigned sfx  = redux_add(fx, 0xffu);
        if (lane == 0) {
            uint4 sl;
            sl.x = mlo;
            sl.y = mx;
            sl.z = sfx;
            sl.w = 1u;                              // flag
            slot_store(&g_slot[(b * N_CLS + w) * CHUNKS + chunk], sl);
        }
    }

    // ------------- Gather blocks: chunk < 8 -> class k = chunk -------------
    if (chunk >= N_CLS) return;
    const int k = chunk;

    uint4* const base = &g_slot[(b * N_CLS + k) * CHUNKS];

    // ALL warps poll redundantly: 32 slots, 1 per lane.
    uint4 r0;
    for (;;) {
        r0 = slot_load(base + lane);
        if (__all_sync(0xffffffffu, r0.w != 0u)) break;
        __nanosleep(32);
    }
    // redux reduce -> every lane ends with the final arg/mask.
    const unsigned mx   = redux_max(r0.y, 0xffffffffu);
    const unsigned cand = (r0.y == mx) ? r0.x : 0u;
    const unsigned mlo  = redux_max(cand, 0xffffffffu);
    const unsigned tot  = redux_add(r0.z, 0xffffffffu);

    const int   arg  = N_POS - 1 - (int)mlo;
    const float mask = (tot > TAU_FIXED) ? 1.0f : 0.0f;

    // Issue emb loads immediately (critical path).
    const float4* __restrict__ src =
        (const float4*)(emb + ((size_t)b * N_POS + (size_t)arg) * C_DIM);
    float4* __restrict__ dst =
        (float4*)(out + ((size_t)b * N_CLS + (size_t)k) * C_DIM);

    float4 v0 = __ldg(src + t);
    float4 v1 = __ldg(src + t + NTHREADS);

    // Reset own slots off the critical path (hidden under emb load latency).
    __syncthreads();
    if (w == 0) slot_store(base + lane, make_uint4(0u, 0u, 0u, 0u));

    v0.x *= mask; v0.y *= mask; v0.z *= mask; v0.w *= mask;
    v1.x *= mask; v1.y *= mask; v1.z *= mask; v1.w *= mask;
    dst[t]            = v0;
    dst[t + NTHREADS] = v1;
}

extern "C" void kernel_launch(void* const* d_in, const int* in_sizes, int n_in,
                              void* d_out, int out_size)
{
    const float* emb  = (const float*)d_in[0];
    const float* prob = (const float*)d_in[1];
    float* out = (float*)d_out;

    const int B = in_sizes[0] / (N_POS * C_DIM);   // = 2

    mfbd_fused<<<B * CHUNKS, NTHREADS>>>(emb, prob, out);   // 64 blocks, 1 wave
}